// round 8
// baseline (speedup 1.0000x reference)
#include <cuda_runtime.h>
#include <cuda_fp16.h>
#include <cstdint>
#include <cmath>

// ---------------- problem constants ----------------
#define NB   4          // batch N
#define LQ   8192       // queries
#define DIM  256        // model dim
#define NHD  8          // heads
#define NLV  4          // levels
#define NPT  4          // points
#define HD   32         // head dim
#define LIN  21760      // sum of level sizes
#define DFF  1024       // 4*D

__device__ __constant__ int c_lvl_h[4]     = {128, 64, 32, 16};
__device__ __constant__ int c_lvl_w[4]     = {128, 64, 32, 16};
__device__ __constant__ int c_lvl_start[4] = {0, 16384, 20480, 21504};

// ---------------- scratch (device globals, no allocation) ----------------
__device__ float  g_q    [(size_t)NB * LQ * DIM];
__device__ __half g_valh [(size_t)NB * LIN * DIM];   // fp16 value (L2-resident)
__device__ float  g_off  [(size_t)NB * LQ * DIM];
__device__ float  g_aw   [(size_t)NB * LQ * 128];
__device__ float  g_attn [(size_t)NB * LQ * DIM];
__device__ float  g_y    [(size_t)NB * LQ * DIM];
__device__ float  g_x    [(size_t)NB * LQ * DIM];
__device__ float  g_h    [(size_t)NB * LQ * DFF];
__device__ float  g_y2   [(size_t)NB * LQ * DIM];

// ---------------- elementwise add (float4) ----------------
__global__ void add_kernel(const float* __restrict__ a, const float* __restrict__ b,
                           float* __restrict__ o, int n4) {
    int i = blockIdx.x * blockDim.x + threadIdx.x;
    if (i >= n4) return;
    float4 av = ((const float4*)a)[i];
    float4 bv = ((const float4*)b)[i];
    ((float4*)o)[i] = make_float4(av.x + bv.x, av.y + bv.y, av.z + bv.z, av.w + bv.w);
}

// ---------------- TF32 tensor-core GEMM, 2-stage cp.async double buffer -----
// C = A(MxK) @ B(KxN) + bias, epilogues:
//   0: +bias (f32 out)   1: +bias,relu (f32)   2: +bias,+resid (f32)
//   3: +bias, zero masked rows, fp16 out (Ch)
#define BM 128
#define BN 128
#define BK 16
#define ASTR 20
#define BSTR 136
#define A_STAGE (BM * ASTR)
#define B_STAGE (BK * BSTR)
#define STAGE_F (A_STAGE + B_STAGE)

__device__ __forceinline__ void cp_async16(uint32_t s, const void* g) {
    asm volatile("cp.async.ca.shared.global [%0], [%1], 16;\n" :: "r"(s), "l"(g));
}
__device__ __forceinline__ void cp_commit() {
    asm volatile("cp.async.commit_group;\n");
}
__device__ __forceinline__ void cp_wait0() {
    asm volatile("cp.async.wait_group 0;\n");
}

__device__ __forceinline__ void mma_tf32(float* d, const unsigned* a, const unsigned* b) {
    asm volatile(
        "mma.sync.aligned.m16n8k8.row.col.f32.tf32.tf32.f32 "
        "{%0,%1,%2,%3}, {%4,%5,%6,%7}, {%8,%9}, {%0,%1,%2,%3};"
        : "+f"(d[0]), "+f"(d[1]), "+f"(d[2]), "+f"(d[3])
        : "r"(a[0]), "r"(a[1]), "r"(a[2]), "r"(a[3]), "r"(b[0]), "r"(b[1]));
}

__global__ __launch_bounds__(256, 2)
void tgemm_kernel(const float* __restrict__ A, const float* __restrict__ B,
                  const float* __restrict__ bias, const float* __restrict__ resid,
                  const unsigned char* __restrict__ mask,
                  float* __restrict__ C, __half* __restrict__ Ch,
                  int M, int N, int K, int epi) {
    __shared__ float smem[2 * STAGE_F];   // 37888 bytes, static

    const int tid  = threadIdx.x;
    const int warp = tid >> 5;
    const int lane = tid & 31;
    const int wm = warp >> 1;
    const int wn = warp & 1;
    const int gid = lane >> 2;
    const int tig = lane & 3;

    const int cRow = blockIdx.y * BM;
    const int cCol = blockIdx.x * BN;

    const int aRow0 = tid >> 2;
    const int aCol0 = (tid & 3) * 4;
    const int bRow0 = tid >> 5;
    const int bCol0 = (tid & 31) * 4;

    const uint32_t smem_u = (uint32_t)__cvta_generic_to_shared(smem);
    const uint32_t sA0 = smem_u + (uint32_t)(aRow0 * ASTR + aCol0) * 4u;
    const uint32_t sA1 = smem_u + (uint32_t)((aRow0 + 64) * ASTR + aCol0) * 4u;
    const uint32_t sB0 = smem_u + (uint32_t)(A_STAGE + bRow0 * BSTR + bCol0) * 4u;
    const uint32_t sB1 = smem_u + (uint32_t)(A_STAGE + (bRow0 + 8) * BSTR + bCol0) * 4u;

    const float* Ag0 = A + (size_t)(cRow + aRow0) * K + aCol0;
    const float* Ag1 = A + (size_t)(cRow + aRow0 + 64) * K + aCol0;
    const float* Bg0 = B + (size_t)bRow0 * N + cCol + bCol0;
    const float* Bg1 = B + (size_t)(bRow0 + 8) * N + cCol + bCol0;

    float acc[2][8][4];
#pragma unroll
    for (int mi = 0; mi < 2; mi++)
#pragma unroll
        for (int j = 0; j < 8; j++)
#pragma unroll
            for (int r = 0; r < 4; r++) acc[mi][j][r] = 0.f;

    const int nTiles = K / BK;

    auto issue = [&](int kt, int buf) {
        const uint32_t so = (uint32_t)(buf * STAGE_F) * 4u;
        const int k0 = kt * BK;
        cp_async16(sA0 + so, Ag0 + k0);
        cp_async16(sA1 + so, Ag1 + k0);
        cp_async16(sB0 + so, Bg0 + (size_t)k0 * N);
        cp_async16(sB1 + so, Bg1 + (size_t)k0 * N);
        cp_commit();
    };

    issue(0, 0);

    for (int kt = 0; kt < nTiles; kt++) {
        cp_wait0();
        __syncthreads();

        if (kt + 1 < nTiles) issue(kt + 1, (kt + 1) & 1);

        const float* As = smem + (kt & 1) * STAGE_F;
        const float* Bs = As + A_STAGE;

#pragma unroll
        for (int ks = 0; ks < BK; ks += 8) {
            unsigned afr[2][4];
#pragma unroll
            for (int mi = 0; mi < 2; mi++) {
                const int mrow = wm * 32 + mi * 16 + gid;
                afr[mi][0] = __float_as_uint(As[mrow * ASTR + ks + tig]);
                afr[mi][1] = __float_as_uint(As[(mrow + 8) * ASTR + ks + tig]);
                afr[mi][2] = __float_as_uint(As[mrow * ASTR + ks + tig + 4]);
                afr[mi][3] = __float_as_uint(As[(mrow + 8) * ASTR + ks + tig + 4]);
            }
            unsigned bfr[8][2];
#pragma unroll
            for (int j = 0; j < 8; j++) {
                const int bcol = wn * 64 + j * 8 + gid;
                bfr[j][0] = __float_as_uint(Bs[(ks + tig) * BSTR + bcol]);
                bfr[j][1] = __float_as_uint(Bs[(ks + tig + 4) * BSTR + bcol]);
            }
#pragma unroll
            for (int mi = 0; mi < 2; mi++)
#pragma unroll
                for (int j = 0; j < 8; j++)
                    mma_tf32(acc[mi][j], afr[mi], bfr[j]);
        }
    }

    // epilogue
#pragma unroll
    for (int mi = 0; mi < 2; mi++) {
        const int r0 = cRow + wm * 32 + mi * 16 + gid;
        const int r1 = r0 + 8;
        const unsigned char mz0 = (epi == 3) ? mask[r0] : 0;
        const unsigned char mz1 = (epi == 3) ? mask[r1] : 0;
#pragma unroll
        for (int j = 0; j < 8; j++) {
            const int col = cCol + wn * 64 + j * 8 + tig * 2;
            const float b0 = bias[col], b1 = bias[col + 1];
            float v0 = acc[mi][j][0] + b0;
            float v1 = acc[mi][j][1] + b1;
            float v2 = acc[mi][j][2] + b0;
            float v3 = acc[mi][j][3] + b1;
            if (epi == 1) {
                v0 = fmaxf(v0, 0.f); v1 = fmaxf(v1, 0.f);
                v2 = fmaxf(v2, 0.f); v3 = fmaxf(v3, 0.f);
            }
            if (epi == 2) {
                const float2 rr0 = *(const float2*)&resid[(size_t)r0 * N + col];
                const float2 rr1 = *(const float2*)&resid[(size_t)r1 * N + col];
                v0 += rr0.x; v1 += rr0.y; v2 += rr1.x; v3 += rr1.y;
            }
            if (epi == 3) {
                if (mz0) { v0 = 0.f; v1 = 0.f; }
                if (mz1) { v2 = 0.f; v3 = 0.f; }
                *(__half2*)&Ch[(size_t)r0 * N + col] = __floats2half2_rn(v0, v1);
                *(__half2*)&Ch[(size_t)r1 * N + col] = __floats2half2_rn(v2, v3);
            } else {
                *(float2*)&C[(size_t)r0 * N + col] = make_float2(v0, v1);
                *(float2*)&C[(size_t)r1 * N + col] = make_float2(v2, v3);
            }
        }
    }
}

// ---------------- softmax over groups of 16 ----------------
__global__ void softmax16_kernel(float* __restrict__ aw, int total) {
    int g = blockIdx.x * blockDim.x + threadIdx.x;
    if (g >= total) return;
    float* p = aw + (size_t)g * 16;
    float v[16];
    float m = -1e30f;
#pragma unroll
    for (int i = 0; i < 16; i++) { v[i] = p[i]; m = fmaxf(m, v[i]); }
    float s = 0.f;
#pragma unroll
    for (int i = 0; i < 16; i++) { v[i] = expf(v[i] - m); s += v[i]; }
    float inv = 1.f / s;
#pragma unroll
    for (int i = 0; i < 16; i++) p[i] = v[i] * inv;
}

// ---------------- deformable sampling: warp per (n,lq,head), fp16 value ----
__global__ __launch_bounds__(256)
void sample_kernel(const float* __restrict__ refp, float* __restrict__ out) {
    const int warp_global = (blockIdx.x * blockDim.x + threadIdx.x) >> 5;
    const int lane = threadIdx.x & 31;
    if (warp_global >= NB * LQ * NHD) return;

    const int h = warp_global & (NHD - 1);
    const int q = warp_global >> 3;
    const int n = q >> 13;

    const float* offp  = g_off + (size_t)q * 256 + h * 32;
    const float* awp   = g_aw  + (size_t)q * 128 + h * 16;
    const float* ref   = refp  + (size_t)q * (NLV * 2);
    const __half* vbase = g_valh + (size_t)n * LIN * DIM + h * HD + lane;

    float accum = 0.f;
#pragma unroll
    for (int l = 0; l < NLV; l++) {
        const int H = c_lvl_h[l], W = c_lvl_w[l];
        const float rx = ref[l * 2 + 0];
        const float ry = ref[l * 2 + 1];
        const __half* vl = vbase + (size_t)c_lvl_start[l] * DIM;
#pragma unroll
        for (int p = 0; p < NPT; p++) {
            const float ox = offp[(l * 4 + p) * 2 + 0];
            const float oy = offp[(l * 4 + p) * 2 + 1];
            const float a  = awp[l * 4 + p];
            const float x = (rx + ox / (float)W) * (float)W - 0.5f;
            const float y = (ry + oy / (float)H) * (float)H - 0.5f;
            const float x0 = floorf(x), y0 = floorf(y);
            const float dx = x - x0, dy = y - y0;

            const float cxs[4] = {x0, x0 + 1.f, x0,       x0 + 1.f};
            const float cys[4] = {y0, y0,       y0 + 1.f, y0 + 1.f};
            const float ws[4]  = {(1.f - dx) * (1.f - dy), dx * (1.f - dy),
                                  (1.f - dx) * dy,         dx * dy};
#pragma unroll
            for (int c = 0; c < 4; c++) {
                const float cx = cxs[c], cy = cys[c];
                const bool valid = (cx >= 0.f) && (cx <= (float)(W - 1)) &&
                                   (cy >= 0.f) && (cy <= (float)(H - 1));
                if (valid) {
                    const int ix = (int)fminf(fmaxf(cx, 0.f), (float)(W - 1));
                    const int iy = (int)fminf(fmaxf(cy, 0.f), (float)(H - 1));
                    const float v = __half2float(vl[(size_t)(iy * W + ix) * DIM]);
                    accum = fmaf(a * ws[c], v, accum);
                }
            }
        }
    }
    out[(size_t)q * DIM + h * HD + lane] = accum;
}

// ---------------- layernorm: warp per row, D=256 ----------------
__global__ __launch_bounds__(256)
void ln_kernel(const float* __restrict__ in, const float* __restrict__ gam,
               const float* __restrict__ bet, float* __restrict__ out, int rows) {
    const int warp = (blockIdx.x * blockDim.x + threadIdx.x) >> 5;
    const int lane = threadIdx.x & 31;
    if (warp >= rows) return;
    const float* r = in + (size_t)warp * DIM;
    float v[8];
    float s = 0.f;
#pragma unroll
    for (int j = 0; j < 8; j++) { v[j] = r[j * 32 + lane]; s += v[j]; }
#pragma unroll
    for (int o = 16; o > 0; o >>= 1) s += __shfl_xor_sync(0xffffffffu, s, o);
    const float mean = s * (1.f / 256.f);
    float s2 = 0.f;
#pragma unroll
    for (int j = 0; j < 8; j++) { const float d = v[j] - mean; s2 += d * d; }
#pragma unroll
    for (int o = 16; o > 0; o >>= 1) s2 += __shfl_xor_sync(0xffffffffu, s2, o);
    const float rs = rsqrtf(s2 * (1.f / 256.f) + 1e-5f);
    float* ow = out + (size_t)warp * DIM;
#pragma unroll
    for (int j = 0; j < 8; j++) {
        const int c = j * 32 + lane;
        ow[c] = (v[j] - mean) * rs * gam[c] + bet[c];
    }
}

// ---------------- host launch ----------------
extern "C" void kernel_launch(void* const* d_in, const int* in_sizes, int n_in,
                              void* d_out, int out_size) {
    const float* tgt   = (const float*)d_in[0];
    const float* qpos  = (const float*)d_in[1];
    const float* refp  = (const float*)d_in[2];
    const float* src   = (const float*)d_in[3];
    const unsigned char* mask = (const unsigned char*)d_in[6];
    const float* W_off = (const float*)d_in[7];
    const float* b_off = (const float*)d_in[8];
    const float* W_att = (const float*)d_in[9];
    const float* b_att = (const float*)d_in[10];
    const float* W_val = (const float*)d_in[11];
    const float* b_val = (const float*)d_in[12];
    const float* W_out = (const float*)d_in[13];
    const float* b_out = (const float*)d_in[14];
    const float* ln1_g = (const float*)d_in[15];
    const float* ln1_b = (const float*)d_in[16];
    const float* W_fc1 = (const float*)d_in[17];
    const float* b_fc1 = (const float*)d_in[18];
    const float* W_fc2 = (const float*)d_in[19];
    const float* b_fc2 = (const float*)d_in[20];
    const float* ln2_g = (const float*)d_in[21];
    const float* ln2_b = (const float*)d_in[22];
    float* outp = (float*)d_out;

    float *pq, *poff, *paw, *pattn, *py, *px, *ph, *py2;
    __half* pvalh;
    cudaGetSymbolAddress((void**)&pq, g_q);
    cudaGetSymbolAddress((void**)&pvalh, g_valh);
    cudaGetSymbolAddress((void**)&poff, g_off);
    cudaGetSymbolAddress((void**)&paw, g_aw);
    cudaGetSymbolAddress((void**)&pattn, g_attn);
    cudaGetSymbolAddress((void**)&py, g_y);
    cudaGetSymbolAddress((void**)&px, g_x);
    cudaGetSymbolAddress((void**)&ph, g_h);
    cudaGetSymbolAddress((void**)&py2, g_y2);

    const int MQ = NB * LQ;          // 32768
    const int MV = NB * LIN;         // 87040

    // 1. q = tgt + query_pos
    {
        int n4 = MQ * DIM / 4;
        add_kernel<<<(n4 + 255) / 256, 256>>>(tgt, qpos, pq, n4);
    }
    // 2. value = src @ W_val + b_val  (mask rows to zero, fp16 out)
    {
        dim3 grid(DIM / BN, MV / BM);
        tgemm_kernel<<<grid, 256>>>(src, W_val, b_val, nullptr, mask,
                                    nullptr, pvalh, MV, DIM, DIM, 3);
    }
    // 3. off = q @ W_off + b_off
    {
        dim3 grid(DIM / BN, MQ / BM);
        tgemm_kernel<<<grid, 256>>>(pq, W_off, b_off, nullptr, nullptr,
                                    poff, nullptr, MQ, DIM, DIM, 0);
    }
    // 4. aw_raw = q @ W_attn + b_attn
    {
        dim3 grid(128 / BN, MQ / BM);
        tgemm_kernel<<<grid, 256>>>(pq, W_att, b_att, nullptr, nullptr,
                                    paw, nullptr, MQ, 128, DIM, 0);
    }
    // 5. softmax over groups of 16
    {
        int total = MQ * NHD;
        softmax16_kernel<<<(total + 255) / 256, 256>>>(paw, total);
    }
    // 6. deformable sampling -> g_attn
    {
        int total_warps = MQ * NHD;
        int blocks = (total_warps * 32 + 255) / 256;
        sample_kernel<<<blocks, 256>>>(refp, pattn);
    }
    // 7. y = tgt + (attn @ W_out + b_out)
    {
        dim3 grid(DIM / BN, MQ / BM);
        tgemm_kernel<<<grid, 256>>>(pattn, W_out, b_out, tgt, nullptr,
                                    py, nullptr, MQ, DIM, DIM, 2);
    }
    // 8. x = LN1(y)
    {
        int blocks = (MQ * 32 + 255) / 256;
        ln_kernel<<<blocks, 256>>>(py, ln1_g, ln1_b, px, MQ);
    }
    // 9. h = relu(x @ W_fc1 + b_fc1)
    {
        dim3 grid(DFF / BN, MQ / BM);
        tgemm_kernel<<<grid, 256>>>(px, W_fc1, b_fc1, nullptr, nullptr,
                                    ph, nullptr, MQ, DFF, DIM, 1);
    }
    // 10. y2 = x + (h @ W_fc2 + b_fc2)
    {
        dim3 grid(DIM / BN, MQ / BM);
        tgemm_kernel<<<grid, 256>>>(ph, W_fc2, b_fc2, px, nullptr,
                                    py2, nullptr, MQ, DIM, DFF, 2);
    }
    // 11. out = LN2(y2)
    {
        int blocks = (MQ * 32 + 255) / 256;
        ln_kernel<<<blocks, 256>>>(py2, ln2_g, ln2_b, outp, MQ);
    }
}

// round 9
// speedup vs baseline: 1.6282x; 1.6282x over previous
#include <cuda_runtime.h>
#include <cuda_fp16.h>
#include <cstdint>
#include <cmath>

// ---------------- problem constants ----------------
#define NB   4          // batch N
#define LQ   8192       // queries
#define DIM  256        // model dim
#define NHD  8          // heads
#define NLV  4          // levels
#define NPT  4          // points
#define HD   32         // head dim
#define LIN  21760      // sum of level sizes
#define DFF  1024       // 4*D

__device__ __constant__ int c_lvl_h[4]     = {128, 64, 32, 16};
__device__ __constant__ int c_lvl_w[4]     = {128, 64, 32, 16};
__device__ __constant__ int c_lvl_start[4] = {0, 16384, 20480, 21504};

// ---------------- scratch (device globals, no allocation) ----------------
__device__ float  g_q    [(size_t)NB * LQ * DIM];
__device__ __half g_valh [(size_t)NB * LIN * DIM];   // fp16 value (L2-resident)
__device__ float  g_off  [(size_t)NB * LQ * DIM];
__device__ float  g_aw   [(size_t)NB * LQ * 128];
__device__ float  g_attn [(size_t)NB * LQ * DIM];
__device__ float  g_y    [(size_t)NB * LQ * DIM];
__device__ float  g_x    [(size_t)NB * LQ * DIM];
__device__ float  g_h    [(size_t)NB * LQ * DFF];
__device__ float  g_y2   [(size_t)NB * LQ * DIM];

// ---------------- elementwise add (float4) ----------------
__global__ void add_kernel(const float* __restrict__ a, const float* __restrict__ b,
                           float* __restrict__ o, int n4) {
    int i = blockIdx.x * blockDim.x + threadIdx.x;
    if (i >= n4) return;
    float4 av = ((const float4*)a)[i];
    float4 bv = ((const float4*)b)[i];
    ((float4*)o)[i] = make_float4(av.x + bv.x, av.y + bv.y, av.z + bv.z, av.w + bv.w);
}

// ---------------- TF32 tensor-core GEMM, 2-stage cp.async double buffer -----
#define BM 128
#define BN 128
#define BK 16
#define ASTR 20
#define BSTR 136
#define A_STAGE (BM * ASTR)
#define B_STAGE (BK * BSTR)
#define STAGE_F (A_STAGE + B_STAGE)

__device__ __forceinline__ void cp_async16(uint32_t s, const void* g) {
    asm volatile("cp.async.ca.shared.global [%0], [%1], 16;\n" :: "r"(s), "l"(g));
}
__device__ __forceinline__ void cp_commit() {
    asm volatile("cp.async.commit_group;\n");
}
__device__ __forceinline__ void cp_wait0() {
    asm volatile("cp.async.wait_group 0;\n");
}

__device__ __forceinline__ void mma_tf32(float* d, const unsigned* a, const unsigned* b) {
    asm volatile(
        "mma.sync.aligned.m16n8k8.row.col.f32.tf32.tf32.f32 "
        "{%0,%1,%2,%3}, {%4,%5,%6,%7}, {%8,%9}, {%0,%1,%2,%3};"
        : "+f"(d[0]), "+f"(d[1]), "+f"(d[2]), "+f"(d[3])
        : "r"(a[0]), "r"(a[1]), "r"(a[2]), "r"(a[3]), "r"(b[0]), "r"(b[1]));
}

__global__ __launch_bounds__(256, 2)
void tgemm_kernel(const float* __restrict__ A, const float* __restrict__ B,
                  const float* __restrict__ bias, const float* __restrict__ resid,
                  const unsigned char* __restrict__ mask,
                  float* __restrict__ C, __half* __restrict__ Ch,
                  int M, int N, int K, int epi) {
    __shared__ float smem[2 * STAGE_F];

    const int tid  = threadIdx.x;
    const int warp = tid >> 5;
    const int lane = tid & 31;
    const int wm = warp >> 1;
    const int wn = warp & 1;
    const int gid = lane >> 2;
    const int tig = lane & 3;

    const int cRow = blockIdx.y * BM;
    const int cCol = blockIdx.x * BN;

    const int aRow0 = tid >> 2;
    const int aCol0 = (tid & 3) * 4;
    const int bRow0 = tid >> 5;
    const int bCol0 = (tid & 31) * 4;

    const uint32_t smem_u = (uint32_t)__cvta_generic_to_shared(smem);
    const uint32_t sA0 = smem_u + (uint32_t)(aRow0 * ASTR + aCol0) * 4u;
    const uint32_t sA1 = smem_u + (uint32_t)((aRow0 + 64) * ASTR + aCol0) * 4u;
    const uint32_t sB0 = smem_u + (uint32_t)(A_STAGE + bRow0 * BSTR + bCol0) * 4u;
    const uint32_t sB1 = smem_u + (uint32_t)(A_STAGE + (bRow0 + 8) * BSTR + bCol0) * 4u;

    const float* Ag0 = A + (size_t)(cRow + aRow0) * K + aCol0;
    const float* Ag1 = A + (size_t)(cRow + aRow0 + 64) * K + aCol0;
    const float* Bg0 = B + (size_t)bRow0 * N + cCol + bCol0;
    const float* Bg1 = B + (size_t)(bRow0 + 8) * N + cCol + bCol0;

    float acc[2][8][4];
#pragma unroll
    for (int mi = 0; mi < 2; mi++)
#pragma unroll
        for (int j = 0; j < 8; j++)
#pragma unroll
            for (int r = 0; r < 4; r++) acc[mi][j][r] = 0.f;

    const int nTiles = K / BK;

    auto issue = [&](int kt, int buf) {
        const uint32_t so = (uint32_t)(buf * STAGE_F) * 4u;
        const int k0 = kt * BK;
        cp_async16(sA0 + so, Ag0 + k0);
        cp_async16(sA1 + so, Ag1 + k0);
        cp_async16(sB0 + so, Bg0 + (size_t)k0 * N);
        cp_async16(sB1 + so, Bg1 + (size_t)k0 * N);
        cp_commit();
    };

    issue(0, 0);

    for (int kt = 0; kt < nTiles; kt++) {
        cp_wait0();
        __syncthreads();

        if (kt + 1 < nTiles) issue(kt + 1, (kt + 1) & 1);

        const float* As = smem + (kt & 1) * STAGE_F;
        const float* Bs = As + A_STAGE;

#pragma unroll
        for (int ks = 0; ks < BK; ks += 8) {
            unsigned afr[2][4];
#pragma unroll
            for (int mi = 0; mi < 2; mi++) {
                const int mrow = wm * 32 + mi * 16 + gid;
                afr[mi][0] = __float_as_uint(As[mrow * ASTR + ks + tig]);
                afr[mi][1] = __float_as_uint(As[(mrow + 8) * ASTR + ks + tig]);
                afr[mi][2] = __float_as_uint(As[mrow * ASTR + ks + tig + 4]);
                afr[mi][3] = __float_as_uint(As[(mrow + 8) * ASTR + ks + tig + 4]);
            }
            unsigned bfr[8][2];
#pragma unroll
            for (int j = 0; j < 8; j++) {
                const int bcol = wn * 64 + j * 8 + gid;
                bfr[j][0] = __float_as_uint(Bs[(ks + tig) * BSTR + bcol]);
                bfr[j][1] = __float_as_uint(Bs[(ks + tig + 4) * BSTR + bcol]);
            }
#pragma unroll
            for (int mi = 0; mi < 2; mi++)
#pragma unroll
                for (int j = 0; j < 8; j++)
                    mma_tf32(acc[mi][j], afr[mi], bfr[j]);
        }
    }

    // epilogue
#pragma unroll
    for (int mi = 0; mi < 2; mi++) {
        const int r0 = cRow + wm * 32 + mi * 16 + gid;
        const int r1 = r0 + 8;
        const unsigned char mz0 = (epi == 3) ? mask[r0] : 0;
        const unsigned char mz1 = (epi == 3) ? mask[r1] : 0;
#pragma unroll
        for (int j = 0; j < 8; j++) {
            const int col = cCol + wn * 64 + j * 8 + tig * 2;
            const float b0 = bias[col], b1 = bias[col + 1];
            float v0 = acc[mi][j][0] + b0;
            float v1 = acc[mi][j][1] + b1;
            float v2 = acc[mi][j][2] + b0;
            float v3 = acc[mi][j][3] + b1;
            if (epi == 1) {
                v0 = fmaxf(v0, 0.f); v1 = fmaxf(v1, 0.f);
                v2 = fmaxf(v2, 0.f); v3 = fmaxf(v3, 0.f);
            }
            if (epi == 2) {
                const float2 rr0 = *(const float2*)&resid[(size_t)r0 * N + col];
                const float2 rr1 = *(const float2*)&resid[(size_t)r1 * N + col];
                v0 += rr0.x; v1 += rr0.y; v2 += rr1.x; v3 += rr1.y;
            }
            if (epi == 3) {
                if (mz0) { v0 = 0.f; v1 = 0.f; }
                if (mz1) { v2 = 0.f; v3 = 0.f; }
                *(__half2*)&Ch[(size_t)r0 * N + col] = __floats2half2_rn(v0, v1);
                *(__half2*)&Ch[(size_t)r1 * N + col] = __floats2half2_rn(v2, v3);
            } else {
                *(float2*)&C[(size_t)r0 * N + col] = make_float2(v0, v1);
                *(float2*)&C[(size_t)r1 * N + col] = make_float2(v2, v3);
            }
        }
    }
}

// ---------------- softmax over groups of 16 ----------------
__global__ void softmax16_kernel(float* __restrict__ aw, int total) {
    int g = blockIdx.x * blockDim.x + threadIdx.x;
    if (g >= total) return;
    float* p = aw + (size_t)g * 16;
    float v[16];
    float m = -1e30f;
#pragma unroll
    for (int i = 0; i < 16; i++) { v[i] = p[i]; m = fmaxf(m, v[i]); }
    float s = 0.f;
#pragma unroll
    for (int i = 0; i < 16; i++) { v[i] = expf(v[i] - m); s += v[i]; }
    float inv = 1.f / s;
#pragma unroll
    for (int i = 0; i < 16; i++) p[i] = v[i] * inv;
}

// ---------------- deformable sampling v2 ------------------------------------
// One warp processes ONE query x TWO heads.
//   Math phase: each lane computes address+weights for one (head-half, point):
//     lane = hh*16 + p  (hh in {0,1}, p in 0..15)
//   Gather phase: lane = hh*16 + ch (ch = channel pair), reads (idx, w) for
//     point p of its head-half via shfl from lane (hh*16 + p), loads __half2.
// Branch-free: corners clamped, weight zeroed when invalid, aw folded in.
__global__ __launch_bounds__(256)
void sample_kernel(const float* __restrict__ refp, float* __restrict__ out) {
    const int warp_global = (blockIdx.x * blockDim.x + threadIdx.x) >> 5;
    const int lane = threadIdx.x & 31;
    if (warp_global >= NB * LQ * (NHD / 2)) return;

    const int h2 = warp_global & 3;          // head pair 0..3
    const int q  = warp_global >> 2;         // n*LQ + lq
    const int n  = q >> 13;                  // LQ = 8192

    // ---------- math phase: lane -> (head-half hh, point p) ----------
    const int p  = lane & 15;
    const int hh = lane >> 4;
    const int h  = h2 * 2 + hh;
    const int l  = p >> 2;

    const int W = c_lvl_w[l], H = c_lvl_h[l];
    const float rx = refp[(size_t)q * 8 + l * 2 + 0];
    const float ry = refp[(size_t)q * 8 + l * 2 + 1];
    const float ox = g_off[(size_t)q * 256 + h * 32 + p * 2 + 0];
    const float oy = g_off[(size_t)q * 256 + h * 32 + p * 2 + 1];
    const float a  = g_aw [(size_t)q * 128 + h * 16 + p];

    const float x = (rx + ox / (float)W) * (float)W - 0.5f;
    const float y = (ry + oy / (float)H) * (float)H - 0.5f;
    const float x0f = floorf(x), y0f = floorf(y);
    const float dx = x - x0f, dy = y - y0f;

    const int x0 = (int)x0f, y0 = (int)y0f;
    const int x1 = x0 + 1,  y1 = y0 + 1;

    const bool vx0 = (x0 >= 0) & (x0 <= W - 1);
    const bool vx1 = (x1 >= 0) & (x1 <= W - 1);
    const bool vy0 = (y0 >= 0) & (y0 <= H - 1);
    const bool vy1 = (y1 >= 0) & (y1 <= H - 1);

    const int cx0 = min(max(x0, 0), W - 1);
    const int cx1 = min(max(x1, 0), W - 1);
    const int cy0 = min(max(y0, 0), H - 1);
    const int cy1 = min(max(y1, 0), H - 1);

    const int ls = c_lvl_start[l];
    int   i0 = ls + cy0 * W + cx0;
    int   i1 = ls + cy0 * W + cx1;
    int   i2 = ls + cy1 * W + cx0;
    int   i3 = ls + cy1 * W + cx1;
    float w0 = (1.f - dx) * (1.f - dy) * a * (float)(vx0 & vy0);
    float w1 = dx * (1.f - dy) * a * (float)(vx1 & vy0);
    float w2 = (1.f - dx) * dy * a * (float)(vx0 & vy1);
    float w3 = dx * dy * a * (float)(vx1 & vy1);

    // ---------- gather phase: lane -> (head-half hh, channel pair ch) ----------
    const int ch = lane & 15;                 // channels 2*ch, 2*ch+1 of head h
    const __half* vb = g_valh + (size_t)n * LIN * DIM + h * HD + ch * 2;

    float ax = 0.f, ay = 0.f;
#pragma unroll
    for (int pp = 0; pp < 16; pp++) {
        const int src = (lane & 16) | pp;
        const int   j0 = __shfl_sync(0xffffffffu, i0, src);
        const int   j1 = __shfl_sync(0xffffffffu, i1, src);
        const int   j2 = __shfl_sync(0xffffffffu, i2, src);
        const int   j3 = __shfl_sync(0xffffffffu, i3, src);
        const float u0 = __shfl_sync(0xffffffffu, w0, src);
        const float u1 = __shfl_sync(0xffffffffu, w1, src);
        const float u2 = __shfl_sync(0xffffffffu, w2, src);
        const float u3 = __shfl_sync(0xffffffffu, w3, src);

        const __half2 v0 = *(const __half2*)(vb + (size_t)j0 * DIM);
        const __half2 v1 = *(const __half2*)(vb + (size_t)j1 * DIM);
        const __half2 v2 = *(const __half2*)(vb + (size_t)j2 * DIM);
        const __half2 v3 = *(const __half2*)(vb + (size_t)j3 * DIM);

        const float2 f0 = __half22float2(v0);
        const float2 f1 = __half22float2(v1);
        const float2 f2 = __half22float2(v2);
        const float2 f3 = __half22float2(v3);

        ax = fmaf(u0, f0.x, ax); ay = fmaf(u0, f0.y, ay);
        ax = fmaf(u1, f1.x, ax); ay = fmaf(u1, f1.y, ay);
        ax = fmaf(u2, f2.x, ax); ay = fmaf(u2, f2.y, ay);
        ax = fmaf(u3, f3.x, ax); ay = fmaf(u3, f3.y, ay);
    }

    *(float2*)&out[(size_t)q * DIM + h * HD + ch * 2] = make_float2(ax, ay);
}

// ---------------- layernorm: warp per row, D=256 ----------------
__global__ __launch_bounds__(256)
void ln_kernel(const float* __restrict__ in, const float* __restrict__ gam,
               const float* __restrict__ bet, float* __restrict__ out, int rows) {
    const int warp = (blockIdx.x * blockDim.x + threadIdx.x) >> 5;
    const int lane = threadIdx.x & 31;
    if (warp >= rows) return;
    const float* r = in + (size_t)warp * DIM;
    float v[8];
    float s = 0.f;
#pragma unroll
    for (int j = 0; j < 8; j++) { v[j] = r[j * 32 + lane]; s += v[j]; }
#pragma unroll
    for (int o = 16; o > 0; o >>= 1) s += __shfl_xor_sync(0xffffffffu, s, o);
    const float mean = s * (1.f / 256.f);
    float s2 = 0.f;
#pragma unroll
    for (int j = 0; j < 8; j++) { const float d = v[j] - mean; s2 += d * d; }
#pragma unroll
    for (int o = 16; o > 0; o >>= 1) s2 += __shfl_xor_sync(0xffffffffu, s2, o);
    const float rs = rsqrtf(s2 * (1.f / 256.f) + 1e-5f);
    float* ow = out + (size_t)warp * DIM;
#pragma unroll
    for (int j = 0; j < 8; j++) {
        const int c = j * 32 + lane;
        ow[c] = (v[j] - mean) * rs * gam[c] + bet[c];
    }
}

// ---------------- host launch ----------------
extern "C" void kernel_launch(void* const* d_in, const int* in_sizes, int n_in,
                              void* d_out, int out_size) {
    const float* tgt   = (const float*)d_in[0];
    const float* qpos  = (const float*)d_in[1];
    const float* refp  = (const float*)d_in[2];
    const float* src   = (const float*)d_in[3];
    const unsigned char* mask = (const unsigned char*)d_in[6];
    const float* W_off = (const float*)d_in[7];
    const float* b_off = (const float*)d_in[8];
    const float* W_att = (const float*)d_in[9];
    const float* b_att = (const float*)d_in[10];
    const float* W_val = (const float*)d_in[11];
    const float* b_val = (const float*)d_in[12];
    const float* W_out = (const float*)d_in[13];
    const float* b_out = (const float*)d_in[14];
    const float* ln1_g = (const float*)d_in[15];
    const float* ln1_b = (const float*)d_in[16];
    const float* W_fc1 = (const float*)d_in[17];
    const float* b_fc1 = (const float*)d_in[18];
    const float* W_fc2 = (const float*)d_in[19];
    const float* b_fc2 = (const float*)d_in[20];
    const float* ln2_g = (const float*)d_in[21];
    const float* ln2_b = (const float*)d_in[22];
    float* outp = (float*)d_out;

    float *pq, *poff, *paw, *pattn, *py, *px, *ph, *py2;
    __half* pvalh;
    cudaGetSymbolAddress((void**)&pq, g_q);
    cudaGetSymbolAddress((void**)&pvalh, g_valh);
    cudaGetSymbolAddress((void**)&poff, g_off);
    cudaGetSymbolAddress((void**)&paw, g_aw);
    cudaGetSymbolAddress((void**)&pattn, g_attn);
    cudaGetSymbolAddress((void**)&py, g_y);
    cudaGetSymbolAddress((void**)&px, g_x);
    cudaGetSymbolAddress((void**)&ph, g_h);
    cudaGetSymbolAddress((void**)&py2, g_y2);

    const int MQ = NB * LQ;          // 32768
    const int MV = NB * LIN;         // 87040

    // 1. q = tgt + query_pos
    {
        int n4 = MQ * DIM / 4;
        add_kernel<<<(n4 + 255) / 256, 256>>>(tgt, qpos, pq, n4);
    }
    // 2. value = src @ W_val + b_val  (mask rows to zero, fp16 out)
    {
        dim3 grid(DIM / BN, MV / BM);
        tgemm_kernel<<<grid, 256>>>(src, W_val, b_val, nullptr, mask,
                                    nullptr, pvalh, MV, DIM, DIM, 3);
    }
    // 3. off = q @ W_off + b_off
    {
        dim3 grid(DIM / BN, MQ / BM);
        tgemm_kernel<<<grid, 256>>>(pq, W_off, b_off, nullptr, nullptr,
                                    poff, nullptr, MQ, DIM, DIM, 0);
    }
    // 4. aw_raw = q @ W_attn + b_attn
    {
        dim3 grid(128 / BN, MQ / BM);
        tgemm_kernel<<<grid, 256>>>(pq, W_att, b_att, nullptr, nullptr,
                                    paw, nullptr, MQ, 128, DIM, 0);
    }
    // 5. softmax over groups of 16
    {
        int total = MQ * NHD;
        softmax16_kernel<<<(total + 255) / 256, 256>>>(paw, total);
    }
    // 6. deformable sampling -> g_attn  (warp per query x 2 heads)
    {
        int total_warps = MQ * (NHD / 2);              // 131072
        int blocks = (total_warps * 32 + 255) / 256;   // 16384
        sample_kernel<<<blocks, 256>>>(refp, pattn);
    }
    // 7. y = tgt + (attn @ W_out + b_out)
    {
        dim3 grid(DIM / BN, MQ / BM);
        tgemm_kernel<<<grid, 256>>>(pattn, W_out, b_out, tgt, nullptr,
                                    py, nullptr, MQ, DIM, DIM, 2);
    }
    // 8. x = LN1(y)
    {
        int blocks = (MQ * 32 + 255) / 256;
        ln_kernel<<<blocks, 256>>>(py, ln1_g, ln1_b, px, MQ);
    }
    // 9. h = relu(x @ W_fc1 + b_fc1)
    {
        dim3 grid(DFF / BN, MQ / BM);
        tgemm_kernel<<<grid, 256>>>(px, W_fc1, b_fc1, nullptr, nullptr,
                                    ph, nullptr, MQ, DFF, DIM, 1);
    }
    // 10. y2 = x + (h @ W_fc2 + b_fc2)
    {
        dim3 grid(DIM / BN, MQ / BM);
        tgemm_kernel<<<grid, 256>>>(ph, W_fc2, b_fc2, px, nullptr,
                                    py2, nullptr, MQ, DIM, DFF, 2);
    }
    // 11. out = LN2(y2)
    {
        int blocks = (MQ * 32 + 255) / 256;
        ln_kernel<<<blocks, 256>>>(py2, ln2_g, ln2_b, outp, MQ);
    }
}